// round 1
// baseline (speedup 1.0000x reference)
#include <cuda_runtime.h>

#define N_NODES  100000
#define N_EDGES  1600000
#define N_GRAPHS 512
#define HIDDEN   128

// ---------------- scratch (static device globals; no allocation allowed) ----
__device__ float g_deg [N_NODES];
__device__ float g_dinv[N_NODES];
__device__ float g_norm[N_EDGES];
__device__ float g_aggx[N_NODES * 3];
__device__ float g_h   [N_NODES * HIDDEN];   // 51.2 MB
__device__ float g_agg2[N_NODES * HIDDEN];   // 51.2 MB
__device__ float g_gsum[N_GRAPHS];
__device__ float g_gcnt[N_GRAPHS];
__device__ int   g_is64;

// ---------------- helpers ---------------------------------------------------
__device__ __forceinline__ int load_idx(const void* p, long long i, int is64) {
    if (is64) return (int)((const long long*)p)[i];
    return ((const int*)p)[i];
}

// ---------------- K1: detect int32 vs int64 edge_index ----------------------
// edge_index values are uniform in [0,1e5): if buffer were int32, the odd
// 32-bit words would be random nonzero values; if int64 (little-endian), the
// odd words are the high halves == 0.
__global__ void k_detect(const unsigned int* ei) {
    unsigned int orv = 0;
#pragma unroll
    for (int i = 1; i < 32; i += 2) orv |= ei[i];
    g_is64 = (orv == 0u) ? 1 : 0;
}

// ---------------- K2: init --------------------------------------------------
__global__ void k_init() {
    int i = blockIdx.x * blockDim.x + threadIdx.x;
    if (i < N_NODES) {
        g_deg[i] = 1.0f;                 // self-loop contribution to degree
        g_aggx[3 * i + 0] = 0.0f;
        g_aggx[3 * i + 1] = 0.0f;
        g_aggx[3 * i + 2] = 0.0f;
    }
    if (i < N_GRAPHS) { g_gsum[i] = 0.0f; g_gcnt[i] = 0.0f; }
}

// ---------------- K3: degree (scatter ones over dst) ------------------------
__global__ void __launch_bounds__(256) k_deg(const void* ei) {
    int e = blockIdx.x * blockDim.x + threadIdx.x;
    if (e >= N_EDGES) return;
    int is64 = g_is64;
    int d = load_idx(ei, (long long)N_EDGES + e, is64);
    atomicAdd(&g_deg[d], 1.0f);
}

// ---------------- K4: dinv = rsqrt(deg) --------------------------------------
__global__ void k_dinv() {
    int i = blockIdx.x * blockDim.x + threadIdx.x;
    if (i < N_NODES) g_dinv[i] = rsqrtf(g_deg[i]);
}

// ---------------- K5: layer-1 edge aggregation on raw x (3-dim) + norm cache
__global__ void __launch_bounds__(256) k_edge1(const void* ei, const float* __restrict__ x) {
    int e = blockIdx.x * blockDim.x + threadIdx.x;
    if (e >= N_EDGES) return;
    int is64 = g_is64;
    int s = load_idx(ei, e, is64);
    int d = load_idx(ei, (long long)N_EDGES + e, is64);
    float nrm = g_dinv[s] * g_dinv[d];
    g_norm[e] = nrm;
    atomicAdd(&g_aggx[3 * d + 0], x[3 * s + 0] * nrm);
    atomicAdd(&g_aggx[3 * d + 1], x[3 * s + 1] * nrm);
    atomicAdd(&g_aggx[3 * d + 2], x[3 * s + 2] * nrm);
}

// ---------------- K6: node update 1: h = relu((aggx + x*dinv^2) @ W1 + b1) ---
// Also zeroes agg2 for the next layer and accumulates per-graph node counts.
__global__ void __launch_bounds__(128) k_node1(const float* __restrict__ x,
                                               const float* __restrict__ W1,
                                               const float* __restrict__ b1,
                                               const void* batch) {
    int i = blockIdx.x;          // one node per block
    int c = threadIdx.x;         // one output column per thread
    float di = g_dinv[i];
    float sw = di * di;
    float v0 = g_aggx[3 * i + 0] + x[3 * i + 0] * sw;
    float v1 = g_aggx[3 * i + 1] + x[3 * i + 1] * sw;
    float v2 = g_aggx[3 * i + 2] + x[3 * i + 2] * sw;
    float y = fmaf(v0, W1[c], fmaf(v1, W1[HIDDEN + c], fmaf(v2, W1[2 * HIDDEN + c], b1[c])));
    y = fmaxf(y, 0.0f);
    int base = i * HIDDEN;
    g_h[base + c]    = y;
    g_agg2[base + c] = 0.0f;
    if (c == 0) {
        int b = load_idx(batch, i, g_is64);
        atomicAdd(&g_gcnt[b], 1.0f);
    }
}

// ---------------- K7: layer-2 edge aggregation on h (128-dim), warp/edge ----
__global__ void __launch_bounds__(256) k_edge2(const void* ei) {
    long long gt = (long long)blockIdx.x * blockDim.x + threadIdx.x;
    int e    = (int)(gt >> 5);
    int lane = threadIdx.x & 31;
    if (e >= N_EDGES) return;
    int is64 = g_is64;
    int s, d;
    if (is64) {
        s = (int)((const long long*)ei)[e];
        d = (int)((const long long*)ei)[(long long)N_EDGES + e];
    } else {
        s = ((const int*)ei)[e];
        d = ((const int*)ei)[N_EDGES + e];
    }
    float nrm = g_norm[e];
    const float4 hv = *reinterpret_cast<const float4*>(&g_h[s * HIDDEN + (lane << 2)]);
    float* dp = &g_agg2[d * HIDDEN + (lane << 2)];
    atomicAdd(dp + 0, hv.x * nrm);
    atomicAdd(dp + 1, hv.y * nrm);
    atomicAdd(dp + 2, hv.z * nrm);
    atomicAdd(dp + 3, hv.w * nrm);
}

// ---------------- K8: node update 2 fused with pooling + Wc ------------------
// G = agg2 + h*dinv^2 ; y = relu(G @ W2 + b2) ; s = y . Wc ; gsum[batch] += s
// One warp per node; each lane owns 4 output columns (float4 W2 row segments).
__global__ void __launch_bounds__(256) k_node2(const float* __restrict__ W2,
                                               const float* __restrict__ b2,
                                               const float* __restrict__ Wc,
                                               const void* batch) {
    __shared__ float gs[8][HIDDEN];
    int w    = threadIdx.x >> 5;                 // warp in block (0..7)
    int lane = threadIdx.x & 31;
    int node = blockIdx.x * 8 + w;
    if (node >= N_NODES) return;

    float di = g_dinv[node];
    float sw = di * di;
    int base = node * HIDDEN;
#pragma unroll
    for (int j = 0; j < 4; j++) {
        int k = lane + 32 * j;
        gs[w][k] = g_agg2[base + k] + g_h[base + k] * sw;
    }
    __syncwarp();

    int c0 = lane << 2;
    float4 acc = make_float4(b2[c0], b2[c0 + 1], b2[c0 + 2], b2[c0 + 3]);
#pragma unroll 4
    for (int k = 0; k < HIDDEN; k++) {
        float gk = gs[w][k];
        const float4 wv = *reinterpret_cast<const float4*>(&W2[k * HIDDEN + c0]);
        acc.x = fmaf(gk, wv.x, acc.x);
        acc.y = fmaf(gk, wv.y, acc.y);
        acc.z = fmaf(gk, wv.z, acc.z);
        acc.w = fmaf(gk, wv.w, acc.w);
    }
    const float4 wc = *reinterpret_cast<const float4*>(&Wc[c0]);
    float s = fmaxf(acc.x, 0.0f) * wc.x + fmaxf(acc.y, 0.0f) * wc.y +
              fmaxf(acc.z, 0.0f) * wc.z + fmaxf(acc.w, 0.0f) * wc.w;
#pragma unroll
    for (int off = 16; off > 0; off >>= 1)
        s += __shfl_down_sync(0xffffffffu, s, off);
    if (lane == 0) {
        int b = load_idx(batch, node, g_is64);
        atomicAdd(&g_gsum[b], s);
    }
}

// ---------------- K9: final sigmoid ------------------------------------------
__global__ void k_out(float* __restrict__ out, const float* __restrict__ bc) {
    int g = blockIdx.x * blockDim.x + threadIdx.x;
    if (g < N_GRAPHS) {
        float cnt   = fmaxf(g_gcnt[g], 1.0f);
        float logit = g_gsum[g] / cnt + bc[0];
        out[g] = 1.0f / (1.0f + expf(-logit));
    }
}

// ---------------- launch ------------------------------------------------------
extern "C" void kernel_launch(void* const* d_in, const int* in_sizes, int n_in,
                              void* d_out, int out_size) {
    const float* x     = (const float*)d_in[0];
    const void*  ei    = d_in[1];
    const void*  batch = d_in[2];
    const float* W1    = (const float*)d_in[3];
    const float* b1    = (const float*)d_in[4];
    const float* W2    = (const float*)d_in[5];
    const float* b2    = (const float*)d_in[6];
    const float* Wc    = (const float*)d_in[7];
    const float* bc    = (const float*)d_in[8];
    float* out = (float*)d_out;

    k_detect<<<1, 1>>>((const unsigned int*)ei);
    k_init  <<<(N_NODES + 255) / 256, 256>>>();
    k_deg   <<<(N_EDGES + 255) / 256, 256>>>(ei);
    k_dinv  <<<(N_NODES + 255) / 256, 256>>>();
    k_edge1 <<<(N_EDGES + 255) / 256, 256>>>(ei, x);
    k_node1 <<<N_NODES, 128>>>(x, W1, b1, batch);
    // 1 warp per edge, 8 warps (256 thr) per block
    k_edge2 <<<(N_EDGES + 7) / 8, 256>>>(ei);
    k_node2 <<<(N_NODES + 7) / 8, 256>>>(W2, b2, Wc, batch);
    k_out   <<<(N_GRAPHS + 255) / 256, 256>>>(out, bc);
}

// round 2
// speedup vs baseline: 2.1843x; 2.1843x over previous
#include <cuda_runtime.h>

#define N_NODES  100000
#define N_EDGES  1600000
#define N_GRAPHS 512
#define HIDDEN   128
#define NB_SCAN  ((N_NODES + 255) / 256)   // 391 scan blocks

// ---------------- scratch (static device globals) ---------------------------
__device__ int   g_degi[N_NODES];            // in-degree (excl self)
__device__ float g_dinv[N_NODES];
__device__ float g_xs  [N_NODES * 3];        // x * dinv
__device__ int   g_rowstart[N_NODES];
__device__ int   g_cursor  [N_NODES];
__device__ int   g_bsum    [NB_SCAN];
__device__ int   g_csr [N_EDGES];            // src per CSR slot (grouped by dst)
__device__ float g_h   [N_NODES * HIDDEN];   // h1 * dinv  (51.2 MB)
__device__ float g_gsum[N_GRAPHS];
__device__ float g_gcnt[N_GRAPHS];
__device__ int   g_is64;

// ---------------- helpers ----------------------------------------------------
__device__ __forceinline__ int load_idx(const void* p, long long i, int is64) {
    if (is64) return (int)((const long long*)p)[i];
    return ((const int*)p)[i];
}

// ---------------- K: detect int32 vs int64 edge_index ------------------------
__global__ void k_detect(const unsigned int* ei) {
    unsigned int orv = 0;
#pragma unroll
    for (int i = 1; i < 32; i += 2) orv |= ei[i];
    g_is64 = (orv == 0u) ? 1 : 0;
}

// ---------------- K: init -----------------------------------------------------
__global__ void k_init() {
    int i = blockIdx.x * blockDim.x + threadIdx.x;
    if (i < N_NODES) g_degi[i] = 0;
    if (i < N_GRAPHS) { g_gsum[i] = 0.0f; g_gcnt[i] = 0.0f; }
}

// ---------------- K: degree histogram over dst --------------------------------
__global__ void __launch_bounds__(256) k_deg(const void* ei) {
    int e = blockIdx.x * blockDim.x + threadIdx.x;
    if (e >= N_EDGES) return;
    int d = load_idx(ei, (long long)N_EDGES + e, g_is64);
    atomicAdd(&g_degi[d], 1);
}

// ---------------- K: dinv + pre-scaled x --------------------------------------
__global__ void k_dinv(const float* __restrict__ x) {
    int i = blockIdx.x * blockDim.x + threadIdx.x;
    if (i >= N_NODES) return;
    float dd = rsqrtf((float)(g_degi[i] + 1));   // +1 self-loop
    g_dinv[i] = dd;
    g_xs[3 * i + 0] = x[3 * i + 0] * dd;
    g_xs[3 * i + 1] = x[3 * i + 1] * dd;
    g_xs[3 * i + 2] = x[3 * i + 2] * dd;
}

// ---------------- scan: A) per-block exclusive scan of degrees ----------------
__global__ void __launch_bounds__(256) k_scanA() {
    __shared__ int wsum[8];
    int tid = threadIdx.x, w = tid >> 5, lane = tid & 31;
    int i = blockIdx.x * 256 + tid;
    int v = (i < N_NODES) ? g_degi[i] : 0;
    int x = v;
#pragma unroll
    for (int off = 1; off < 32; off <<= 1) {
        int y = __shfl_up_sync(0xffffffffu, x, off);
        if (lane >= off) x += y;
    }
    if (lane == 31) wsum[w] = x;
    __syncthreads();
    if (tid == 0) {
        int run = 0;
#pragma unroll
        for (int k = 0; k < 8; k++) { int t = wsum[k]; wsum[k] = run; run += t; }
        g_bsum[blockIdx.x] = run;
    }
    __syncthreads();
    if (i < N_NODES) g_rowstart[i] = (x - v) + wsum[w];
}

// ---------------- scan: B) exclusive scan of block sums (single block) --------
__global__ void __launch_bounds__(512) k_scanB() {
    __shared__ int wsum[16];
    int tid = threadIdx.x, w = tid >> 5, lane = tid & 31;
    int v = (tid < NB_SCAN) ? g_bsum[tid] : 0;
    int x = v;
#pragma unroll
    for (int off = 1; off < 32; off <<= 1) {
        int y = __shfl_up_sync(0xffffffffu, x, off);
        if (lane >= off) x += y;
    }
    if (lane == 31) wsum[w] = x;
    __syncthreads();
    if (tid == 0) {
        int run = 0;
#pragma unroll
        for (int k = 0; k < 16; k++) { int t = wsum[k]; wsum[k] = run; run += t; }
    }
    __syncthreads();
    if (tid < NB_SCAN) g_bsum[tid] = (x - v) + wsum[w];
}

// ---------------- scan: C) add block offsets, init cursors --------------------
__global__ void __launch_bounds__(256) k_scanC() {
    int i = blockIdx.x * 256 + threadIdx.x;
    if (i >= N_NODES) return;
    int r = g_rowstart[i] + g_bsum[blockIdx.x];
    g_rowstart[i] = r;
    g_cursor[i] = r;
}

// ---------------- K: fill CSR --------------------------------------------------
__global__ void __launch_bounds__(256) k_fill(const void* ei) {
    int e = blockIdx.x * blockDim.x + threadIdx.x;
    if (e >= N_EDGES) return;
    int is64 = g_is64;
    int s = load_idx(ei, e, is64);
    int d = load_idx(ei, (long long)N_EDGES + e, is64);
    int slot = atomicAdd(&g_cursor[d], 1);
    g_csr[slot] = s;
}

// ---------------- K: fused layer 1 (gather x' + GEMV W1) ----------------------
// h'(node) = relu( dinv*(sum_{s in N(node)} x'[s] + x'[node]) @ W1 + b1 ) * dinv
__global__ void __launch_bounds__(256) k_layer1(const float* __restrict__ W1,
                                                const float* __restrict__ b1,
                                                const void* batch) {
    int w = threadIdx.x >> 5, lane = threadIdx.x & 31;
    int node = blockIdx.x * 8 + w;
    if (node >= N_NODES) return;
    int start = g_rowstart[node];
    int deg   = g_degi[node];
    float dd  = g_dinv[node];

    float px = 0.f, py = 0.f, pz = 0.f;
    for (int jb = 0; jb < deg; jb += 32) {
        int j = jb + lane;
        if (j < deg) {
            int s = g_csr[start + j];
            px += g_xs[3 * s + 0];
            py += g_xs[3 * s + 1];
            pz += g_xs[3 * s + 2];
        }
    }
#pragma unroll
    for (int off = 16; off > 0; off >>= 1) {
        px += __shfl_down_sync(0xffffffffu, px, off);
        py += __shfl_down_sync(0xffffffffu, py, off);
        pz += __shfl_down_sync(0xffffffffu, pz, off);
    }
    px = __shfl_sync(0xffffffffu, px, 0);
    py = __shfl_sync(0xffffffffu, py, 0);
    pz = __shfl_sync(0xffffffffu, pz, 0);
    float v0 = dd * (px + g_xs[3 * node + 0]);
    float v1 = dd * (py + g_xs[3 * node + 1]);
    float v2 = dd * (pz + g_xs[3 * node + 2]);

    int c0 = lane << 2;
    const float4 w0 = *(const float4*)&W1[c0];
    const float4 w1 = *(const float4*)&W1[HIDDEN + c0];
    const float4 w2 = *(const float4*)&W1[2 * HIDDEN + c0];
    const float4 bb = *(const float4*)&b1[c0];
    float4 y;
    y.x = fmaf(v0, w0.x, fmaf(v1, w1.x, fmaf(v2, w2.x, bb.x)));
    y.y = fmaf(v0, w0.y, fmaf(v1, w1.y, fmaf(v2, w2.y, bb.y)));
    y.z = fmaf(v0, w0.z, fmaf(v1, w1.z, fmaf(v2, w2.z, bb.z)));
    y.w = fmaf(v0, w0.w, fmaf(v1, w1.w, fmaf(v2, w2.w, bb.w)));
    // relu then pre-scale by dinv for next layer's gather
    y.x = fmaxf(y.x, 0.f) * dd; y.y = fmaxf(y.y, 0.f) * dd;
    y.z = fmaxf(y.z, 0.f) * dd; y.w = fmaxf(y.w, 0.f) * dd;
    *(float4*)&g_h[node * HIDDEN + c0] = y;

    if (lane == 0) {
        int b = load_idx(batch, node, g_is64);
        atomicAdd(&g_gcnt[b], 1.0f);
    }
}

// ---------------- K: fused layer 2 (gather h' + GEMV W2 + Wc + pool) ----------
// G = dinv*(sum h'[s] + h'[node]);  y = relu(G@W2+b2);  gsum[batch] += y.Wc
__global__ void __launch_bounds__(256) k_layer2(const float* __restrict__ W2,
                                                const float* __restrict__ b2,
                                                const float* __restrict__ Wc,
                                                const void* batch) {
    __shared__ float gs[8][HIDDEN];
    int w = threadIdx.x >> 5, lane = threadIdx.x & 31;
    int node = blockIdx.x * 8 + w;
    if (node >= N_NODES) return;
    int start = g_rowstart[node];
    int deg   = g_degi[node];
    float dd  = g_dinv[node];

    const float4* hrows = (const float4*)g_h;   // 32 float4 per row
    float4 acc = __ldg(&hrows[node * 32 + lane]);   // self term h'[node]
    for (int jb = 0; jb < deg; jb += 32) {
        int j = jb + lane;
        int myidx = (j < deg) ? g_csr[start + j] : 0;
        int cnt = min(32, deg - jb);
        for (int t = 0; t < cnt; t++) {
            int s = __shfl_sync(0xffffffffu, myidx, t);
            float4 v = __ldg(&hrows[s * 32 + lane]);
            acc.x += v.x; acc.y += v.y; acc.z += v.z; acc.w += v.w;
        }
    }
    int c0 = lane << 2;
    gs[w][c0 + 0] = acc.x * dd;
    gs[w][c0 + 1] = acc.y * dd;
    gs[w][c0 + 2] = acc.z * dd;
    gs[w][c0 + 3] = acc.w * dd;
    __syncwarp();

    float4 o = *(const float4*)&b2[c0];
#pragma unroll 4
    for (int k = 0; k < HIDDEN; k++) {
        float gk = gs[w][k];
        const float4 wv = __ldg((const float4*)&W2[k * HIDDEN + c0]);
        o.x = fmaf(gk, wv.x, o.x);
        o.y = fmaf(gk, wv.y, o.y);
        o.z = fmaf(gk, wv.z, o.z);
        o.w = fmaf(gk, wv.w, o.w);
    }
    const float4 wc = *(const float4*)&Wc[c0];
    float s = fmaxf(o.x, 0.f) * wc.x + fmaxf(o.y, 0.f) * wc.y +
              fmaxf(o.z, 0.f) * wc.z + fmaxf(o.w, 0.f) * wc.w;
#pragma unroll
    for (int off = 16; off > 0; off >>= 1)
        s += __shfl_down_sync(0xffffffffu, s, off);
    if (lane == 0) {
        int b = load_idx(batch, node, g_is64);
        atomicAdd(&g_gsum[b], s);
    }
}

// ---------------- K: final sigmoid --------------------------------------------
__global__ void k_out(float* __restrict__ out, const float* __restrict__ bc) {
    int g = blockIdx.x * blockDim.x + threadIdx.x;
    if (g < N_GRAPHS) {
        float cnt   = fmaxf(g_gcnt[g], 1.0f);
        float logit = g_gsum[g] / cnt + bc[0];
        out[g] = 1.0f / (1.0f + expf(-logit));
    }
}

// ---------------- launch --------------------------------------------------------
extern "C" void kernel_launch(void* const* d_in, const int* in_sizes, int n_in,
                              void* d_out, int out_size) {
    const float* x     = (const float*)d_in[0];
    const void*  ei    = d_in[1];
    const void*  batch = d_in[2];
    const float* W1    = (const float*)d_in[3];
    const float* b1    = (const float*)d_in[4];
    const float* W2    = (const float*)d_in[5];
    const float* b2    = (const float*)d_in[6];
    const float* Wc    = (const float*)d_in[7];
    const float* bc    = (const float*)d_in[8];
    float* out = (float*)d_out;

    k_detect<<<1, 1>>>((const unsigned int*)ei);
    k_init  <<<(N_NODES + 255) / 256, 256>>>();
    k_deg   <<<(N_EDGES + 255) / 256, 256>>>(ei);
    k_dinv  <<<(N_NODES + 255) / 256, 256>>>(x);
    k_scanA <<<NB_SCAN, 256>>>();
    k_scanB <<<1, 512>>>();
    k_scanC <<<NB_SCAN, 256>>>();
    k_fill  <<<(N_EDGES + 255) / 256, 256>>>(ei);
    k_layer1<<<(N_NODES + 7) / 8, 256>>>(W1, b1, batch);
    k_layer2<<<(N_NODES + 7) / 8, 256>>>(W2, b2, Wc, batch);
    k_out   <<<(N_GRAPHS + 255) / 256, 256>>>(out, bc);
}